// round 1
// baseline (speedup 1.0000x reference)
#include <cuda_runtime.h>
#include <cstdint>

#define Bb   32
#define Ll   2048
#define Dd   768
#define Hh   512
#define BL   (Bb * Ll)          // 65536
#define EPSF 1e-5f

// ---------------- scratch (device globals; no allocations allowed) ----------
__device__ float g_h[(size_t)BL * Hh];   // 128 MiB intermediate h = hidden@W1+b1
__device__ float g_sum[Hh];
__device__ float g_sumsq[Hh];
__device__ float g_scale[Hh];
__device__ float g_shift[Hh];
__device__ float g_pool[Bb * Hh];
__device__ float g_cnt[Bb];              // raw valid-token counts per batch

// ---------------- helpers ----------------------------------------------------
__device__ __forceinline__ uint32_t f2tf32(float x) {
    uint32_t r;
    asm("cvt.rna.tf32.f32 %0, %1;" : "=r"(r) : "f"(x));
    return r;
}

__device__ __forceinline__ void mma1688(float* c, const uint32_t* a, const uint32_t* b) {
    asm volatile(
        "mma.sync.aligned.m16n8k8.row.col.f32.tf32.tf32.f32 "
        "{%0,%1,%2,%3}, {%4,%5,%6,%7}, {%8,%9}, {%0,%1,%2,%3};"
        : "+f"(c[0]), "+f"(c[1]), "+f"(c[2]), "+f"(c[3])
        : "r"(a[0]), "r"(a[1]), "r"(a[2]), "r"(a[3]), "r"(b[0]), "r"(b[1]));
}

// ---------------- K0a: zero accumulators -------------------------------------
__global__ void k_zero() {
    int i = blockIdx.x * blockDim.x + threadIdx.x;
    if (i < Hh) { g_sum[i] = 0.f; g_sumsq[i] = 0.f; }
    if (i < Bb * Hh) g_pool[i] = 0.f;
}

// ---------------- K0b: per-batch valid counts --------------------------------
__global__ void k_counts(const int* __restrict__ mask) {
    __shared__ int red[256];
    int b = blockIdx.x;
    int s = 0;
    for (int l = threadIdx.x; l < Ll; l += 256) s += mask[b * Ll + l];
    red[threadIdx.x] = s;
    __syncthreads();
    for (int off = 128; off; off >>= 1) {
        if (threadIdx.x < off) red[threadIdx.x] += red[threadIdx.x + off];
        __syncthreads();
    }
    if (threadIdx.x == 0) g_cnt[b] = (float)red[0];
}

// ---------------- K1: GEMM1 (tf32 mma.sync) + bias + masked BN stats ---------
// C(128x128 tile) = A(BL x 768) * W1(768 x 512); 8 warps, warp tile 32x64.
__global__ __launch_bounds__(256, 2) void k_gemm1(
    const float* __restrict__ A, const float* __restrict__ W1,
    const float* __restrict__ b1, const int* __restrict__ mask)
{
    __shared__ uint32_t As[16][132];  // [k][m], padded
    __shared__ uint32_t Bs[16][132];  // [k][n], padded
    __shared__ float    Ms[128];      // row masks for this tile

    const int tid  = threadIdx.x;
    const int warp = tid >> 5, lane = tid & 31;
    const int lr = lane >> 2, lc = lane & 3;     // groupID, threadID_in_group
    const int wm = warp & 3,  wn = warp >> 2;    // warp grid 4(M) x 2(N)
    const int rbase = blockIdx.y * 128;
    const int cbase = blockIdx.x * 128;

    if (tid < 128) Ms[tid] = (float)mask[rbase + tid];

    // loader coordinates (two float4 per thread per operand per chunk)
    const int fA0 = tid, fA1 = tid + 256;
    const int arow0 = fA0 >> 2, akq0 = fA0 & 3;
    const int arow1 = fA1 >> 2, akq1 = fA1 & 3;
    const int bkr0 = fA0 >> 5, bcq0 = fA0 & 31;
    const int bkr1 = fA1 >> 5, bcq1 = fA1 & 31;
    const float* Ap0 = A + (size_t)(rbase + arow0) * Dd + akq0 * 4;
    const float* Ap1 = A + (size_t)(rbase + arow1) * Dd + akq1 * 4;
    const float* Bp0 = W1 + (size_t)bkr0 * Hh + cbase + bcq0 * 4;
    const float* Bp1 = W1 + (size_t)bkr1 * Hh + cbase + bcq1 * 4;

    float c[2][8][4];
#pragma unroll
    for (int mt = 0; mt < 2; mt++)
#pragma unroll
        for (int nt = 0; nt < 8; nt++)
#pragma unroll
            for (int i = 0; i < 4; i++) c[mt][nt][i] = 0.f;

    for (int k0 = 0; k0 < Dd; k0 += 16) {
        __syncthreads();
        float4 va0 = *(const float4*)(Ap0 + k0);
        float4 va1 = *(const float4*)(Ap1 + k0);
        float4 vb0 = *(const float4*)(Bp0 + (size_t)k0 * Hh);
        float4 vb1 = *(const float4*)(Bp1 + (size_t)k0 * Hh);
        As[akq0 * 4 + 0][arow0] = f2tf32(va0.x);
        As[akq0 * 4 + 1][arow0] = f2tf32(va0.y);
        As[akq0 * 4 + 2][arow0] = f2tf32(va0.z);
        As[akq0 * 4 + 3][arow0] = f2tf32(va0.w);
        As[akq1 * 4 + 0][arow1] = f2tf32(va1.x);
        As[akq1 * 4 + 1][arow1] = f2tf32(va1.y);
        As[akq1 * 4 + 2][arow1] = f2tf32(va1.z);
        As[akq1 * 4 + 3][arow1] = f2tf32(va1.w);
        Bs[bkr0][bcq0 * 4 + 0] = f2tf32(vb0.x);
        Bs[bkr0][bcq0 * 4 + 1] = f2tf32(vb0.y);
        Bs[bkr0][bcq0 * 4 + 2] = f2tf32(vb0.z);
        Bs[bkr0][bcq0 * 4 + 3] = f2tf32(vb0.w);
        Bs[bkr1][bcq1 * 4 + 0] = f2tf32(vb1.x);
        Bs[bkr1][bcq1 * 4 + 1] = f2tf32(vb1.y);
        Bs[bkr1][bcq1 * 4 + 2] = f2tf32(vb1.z);
        Bs[bkr1][bcq1 * 4 + 3] = f2tf32(vb1.w);
        __syncthreads();

#pragma unroll
        for (int ks = 0; ks < 2; ks++) {
            const int kb = ks * 8;
            uint32_t a[2][4], bf[8][2];
#pragma unroll
            for (int mt = 0; mt < 2; mt++) {
                int r = wm * 32 + mt * 16 + lr;
                a[mt][0] = As[kb + lc][r];
                a[mt][1] = As[kb + lc][r + 8];
                a[mt][2] = As[kb + lc + 4][r];
                a[mt][3] = As[kb + lc + 4][r + 8];
            }
#pragma unroll
            for (int nt = 0; nt < 8; nt++) {
                int n = wn * 64 + nt * 8 + lr;
                bf[nt][0] = Bs[kb + lc][n];
                bf[nt][1] = Bs[kb + lc + 4][n];
            }
#pragma unroll
            for (int mt = 0; mt < 2; mt++)
#pragma unroll
                for (int nt = 0; nt < 8; nt++)
                    mma1688(c[mt][nt], a[mt], bf[nt]);
        }
    }

    // ---------------- epilogue: bias, store h, masked per-channel stats ------
#pragma unroll
    for (int nt = 0; nt < 8; nt++) {
        const int cl0 = wn * 64 + nt * 8 + lc * 2;
        const int gc  = cbase + cl0;
        const float bv0 = b1[gc], bv1 = b1[gc + 1];
        float s0 = 0.f, q0 = 0.f, s1 = 0.f, q1 = 0.f;
#pragma unroll
        for (int mt = 0; mt < 2; mt++) {
            const int r0l = wm * 32 + mt * 16 + lr;
            const float m0 = Ms[r0l], m1 = Ms[r0l + 8];
            const float h00 = c[mt][nt][0] + bv0, h01 = c[mt][nt][1] + bv1;
            const float h10 = c[mt][nt][2] + bv0, h11 = c[mt][nt][3] + bv1;
            *(float2*)(g_h + (size_t)(rbase + r0l) * Hh + gc)     = make_float2(h00, h01);
            *(float2*)(g_h + (size_t)(rbase + r0l + 8) * Hh + gc) = make_float2(h10, h11);
            s0 += m0 * h00 + m1 * h10;
            q0 += m0 * h00 * h00 + m1 * h10 * h10;
            s1 += m0 * h01 + m1 * h11;
            q1 += m0 * h01 * h01 + m1 * h11 * h11;
        }
#pragma unroll
        for (int off = 4; off < 32; off <<= 1) {
            s0 += __shfl_xor_sync(0xffffffffu, s0, off);
            q0 += __shfl_xor_sync(0xffffffffu, q0, off);
            s1 += __shfl_xor_sync(0xffffffffu, s1, off);
            q1 += __shfl_xor_sync(0xffffffffu, q1, off);
        }
        if (lr == 0) {
            atomicAdd(&g_sum[gc], s0);
            atomicAdd(&g_sumsq[gc], q0);
            atomicAdd(&g_sum[gc + 1], s1);
            atomicAdd(&g_sumsq[gc + 1], q1);
        }
    }
}

// ---------------- K2: finalize BN affine -------------------------------------
__global__ void k_stats(const float* __restrict__ gamma, const float* __restrict__ beta) {
    __shared__ float nv;
    if (threadIdx.x == 0) {
        float s = 0.f;
        for (int b = 0; b < Bb; b++) s += g_cnt[b];
        nv = fmaxf(s, 1.f);
    }
    __syncthreads();
    int h = threadIdx.x;
    float mean = g_sum[h] / nv;
    float var  = fmaxf(g_sumsq[h] / nv - mean * mean, 0.f);
    float inv  = rsqrtf(var + EPSF);
    float sc   = inv * gamma[h];
    g_scale[h] = sc;
    g_shift[h] = beta[h] - mean * sc;
}

// ---------------- K3: BN + ReLU + masked pooling over L ----------------------
__global__ __launch_bounds__(256) void k_pool(const int* __restrict__ mask) {
    __shared__ int msk[128];
    const int b = blockIdx.y, lcb = blockIdx.x;
    const int t = threadIdx.x;
    const int rbase = b * Ll + lcb * 128;
    if (t < 128) msk[t] = mask[rbase + t];
    __syncthreads();

    const float sc0 = g_scale[t],       sh0 = g_shift[t];
    const float sc1 = g_scale[t + 256], sh1 = g_shift[t + 256];
    float a0 = 0.f, a1 = 0.f;
#pragma unroll 4
    for (int i = 0; i < 128; i++) {
        if (msk[i]) {
            const float* hp = g_h + (size_t)(rbase + i) * Hh;
            float v0 = hp[t], v1 = hp[t + 256];
            a0 += fmaxf(fmaf(v0, sc0, sh0), 0.f);
            a1 += fmaxf(fmaf(v1, sc1, sh1), 0.f);
        }
    }
    atomicAdd(&g_pool[b * Hh + t], a0);
    atomicAdd(&g_pool[b * Hh + t + 256], a1);
}

// ---------------- K4: tiny GEMM pooled @ W2 + b2 -----------------------------
__global__ __launch_bounds__(512) void k_out(const float* __restrict__ W2,
                                             const float* __restrict__ b2,
                                             float* __restrict__ out) {
    __shared__ float p[Hh];
    const int b = blockIdx.x, t = threadIdx.x;
    const float craw = g_cnt[b];
    p[t] = g_pool[b * Hh + t] / fmaxf(craw, 1.f);
    __syncthreads();
    float acc = (craw > 0.f) ? b2[t] : 0.f;
#pragma unroll 8
    for (int k = 0; k < Hh; k++) acc = fmaf(p[k], W2[(size_t)k * Hh + t], acc);
    out[b * Hh + t] = acc;
}

// ---------------- launch -----------------------------------------------------
extern "C" void kernel_launch(void* const* d_in, const int* in_sizes, int n_in,
                              void* d_out, int out_size) {
    const float* hidden = (const float*)d_in[0];
    const int*   mask   = (const int*)d_in[1];
    const float* W1     = (const float*)d_in[2];
    const float* b1     = (const float*)d_in[3];
    const float* gamma  = (const float*)d_in[4];
    const float* beta   = (const float*)d_in[5];
    const float* W2     = (const float*)d_in[6];
    const float* b2     = (const float*)d_in[7];
    float*       out    = (float*)d_out;

    k_zero<<<(Bb * Hh + 255) / 256, 256>>>();
    k_counts<<<Bb, 256>>>(mask);
    k_gemm1<<<dim3(Hh / 128, BL / 128), 256>>>(hidden, W1, b1, mask);
    k_stats<<<1, Hh>>>(gamma, beta);
    k_pool<<<dim3(Ll / 128, Bb), 256>>>(mask);
    k_out<<<Bb, Hh>>>(W2, b2, out);
}

// round 4
// speedup vs baseline: 2.5936x; 2.5936x over previous
#include <cuda_runtime.h>
#include <cuda_bf16.h>
#include <cstdint>

#define Bb   32
#define Ll   2048
#define Dd   768
#define Hh   512
#define BL   (Bb * Ll)
#define EPSF 1e-5f
#define NCH  24              // 768 / 32
#define KC   32

// ---------------- scratch ----------------------------------------------------
__device__ __nv_bfloat16 g_wbf[(size_t)Hh * Dd];     // W1^T [N=512][K=768] bf16
__device__ __nv_bfloat16 g_hbf[(size_t)(BL + 128) * Hh]; // compacted h, bf16
__device__ int   g_ridx[BL + 128];
__device__ int   g_icnt[Bb];
__device__ int   g_off[Bb];
__device__ float g_cnt[Bb];
__device__ float g_sum[Hh], g_sumsq[Hh], g_scale[Hh], g_shift[Hh];
__device__ float g_pool[Bb * Hh];

// ---------------- smem layout (GEMM) -----------------------------------------
#define SMB_STRIDE 8192      // B stage: 128 n-rows x 64 B
#define SMA_OFF    24576     // 3 B stages first
#define SMA_STRIDE 8192      // A stage: 128 m-rows x 64 B
#define SM_EXTRA   40960     // sridx(512B) + sbias(512B)
#define SM_TOT     41984

// ---------------- PTX helpers ------------------------------------------------
__device__ __forceinline__ uint32_t smem_u32(const void* p) {
    uint32_t a;
    asm("{ .reg .u64 t; cvta.to.shared.u64 t, %1; cvt.u32.u64 %0, t; }" : "=r"(a) : "l"(p));
    return a;
}
__device__ __forceinline__ void cp_async16(uint32_t dst, const void* src) {
    asm volatile("cp.async.cg.shared.global [%0], [%1], 16;" :: "r"(dst), "l"(src) : "memory");
}
__device__ __forceinline__ void ldsm4(uint32_t* r, uint32_t addr) {
    asm volatile("ldmatrix.sync.aligned.m8n8.x4.shared.b16 {%0,%1,%2,%3}, [%4];"
                 : "=r"(r[0]), "=r"(r[1]), "=r"(r[2]), "=r"(r[3]) : "r"(addr));
}
__device__ __forceinline__ void mma_bf16(float* c, const uint32_t* a, uint32_t b0, uint32_t b1) {
    asm volatile(
        "mma.sync.aligned.m16n8k16.row.col.f32.bf16.bf16.f32 "
        "{%0,%1,%2,%3}, {%4,%5,%6,%7}, {%8,%9}, {%0,%1,%2,%3};"
        : "+f"(c[0]), "+f"(c[1]), "+f"(c[2]), "+f"(c[3])
        : "r"(a[0]), "r"(a[1]), "r"(a[2]), "r"(a[3]), "r"(b0), "r"(b1));
}

// ---------------- K0: init ---------------------------------------------------
__global__ void k_zero() {
    int i = blockIdx.x * blockDim.x + threadIdx.x;
    if (i < BL + 128) g_ridx[i] = -1;
    if (i < Hh) { g_sum[i] = 0.f; g_sumsq[i] = 0.f; }
    if (i < Bb * Hh) g_pool[i] = 0.f;
}

// ---------------- K1: per-batch counts ---------------------------------------
__global__ void k_counts(const int* __restrict__ mask) {
    __shared__ int red[256];
    int b = blockIdx.x, s = 0;
    for (int l = threadIdx.x; l < Ll; l += 256) s += mask[b * Ll + l];
    red[threadIdx.x] = s;
    __syncthreads();
    for (int off = 128; off; off >>= 1) {
        if (threadIdx.x < off) red[threadIdx.x] += red[threadIdx.x + off];
        __syncthreads();
    }
    if (threadIdx.x == 0) { g_icnt[b] = red[0]; g_cnt[b] = (float)red[0]; }
}

// ---------------- K2: exclusive offsets (1 warp) ------------------------------
__global__ void k_offsets() {
    int l = threadIdx.x;
    int c = g_icnt[l], x = c;
    for (int o = 1; o < 32; o <<= 1) {
        int y = __shfl_up_sync(0xffffffffu, x, o);
        if (l >= o) x += y;
    }
    g_off[l] = x - c;
}

// ---------------- K3: stable compaction --------------------------------------
__global__ void k_compact(const int* __restrict__ mask) {
    __shared__ int wsum[8];
    __shared__ int sbase;
    int b = blockIdx.x, t = threadIdx.x, w = t >> 5, l = t & 31;
    if (t == 0) sbase = g_off[b];
    __syncthreads();
    for (int r = 0; r < 8; r++) {
        int gi = b * Ll + r * 256 + t;
        int v = mask[gi];
        int x = v;
        for (int o = 1; o < 32; o <<= 1) {
            int y = __shfl_up_sync(0xffffffffu, x, o);
            if (l >= o) x += y;
        }
        if (l == 31) wsum[w] = x;
        __syncthreads();
        int wpre = 0;
        for (int i = 0; i < w; i++) wpre += wsum[i];
        if (v) g_ridx[sbase + wpre + x - v] = gi;
        __syncthreads();
        if (t == 0) { int s = 0; for (int i = 0; i < 8; i++) s += wsum[i]; sbase += s; }
        __syncthreads();
    }
}

// ---------------- K4: W1 transpose -> bf16 [N][K] ----------------------------
__global__ void k_cvtW(const float* __restrict__ W1) {
    __shared__ float tile[32][33];
    int kb = blockIdx.x * 32, nb = blockIdx.y * 32;
    int tx = threadIdx.x & 31, ty = threadIdx.x >> 5;  // 32 x 8
#pragma unroll
    for (int j = 0; j < 4; j++)
        tile[ty + 8 * j][tx] = W1[(size_t)(kb + ty + 8 * j) * Hh + nb + tx];
    __syncthreads();
#pragma unroll
    for (int j = 0; j < 4; j++)
        g_wbf[(size_t)(nb + ty + 8 * j) * Dd + kb + tx] = __float2bfloat16(tile[tx][ty + 8 * j]);
}

// ---------------- K5: bf16 mma.sync GEMM + bias + fused stats ----------------
__global__ __launch_bounds__(256, 2) void k_gemm(const float* __restrict__ A,
                                                 const float* __restrict__ b1) {
    extern __shared__ char smem[];
    const uint32_t sb = smem_u32(smem);
    const int tid = threadIdx.x;
    const int w = tid >> 5, lane = tid & 31;
    const int lr = lane >> 2, lc = lane & 3;
    const int wm = w & 3, wn = w >> 2;
    const int rbase = blockIdx.y * 128;
    const int cbase = blockIdx.x * 128;

    int*   sridx = (int*)(smem + SM_EXTRA);
    float* sbias = (float*)(smem + SM_EXTRA + 512);
    if (tid < 128) { sridx[tid] = g_ridx[rbase + tid]; sbias[tid] = b1[cbase + tid]; }
    __syncthreads();
    if (sridx[0] < 0) return;   // uniform: whole tile is padding

    // ---- per-thread loader precompute ----
    const float* pA[4]; uint32_t aoff[4];
#pragma unroll
    for (int i = 0; i < 4; i++) {
        int u = tid + i * 256, row = u >> 3, q = u & 7;
        int ridx = sridx[row]; if (ridx < 0) ridx = 0;
        pA[i] = A + (size_t)ridx * Dd + q * 4;
        int c = q >> 1, sub = q & 1;
        aoff[i] = row * 64 + ((c ^ ((row >> 1) & 3)) << 4) + sub * 8;
    }
    const __nv_bfloat16* pB[2]; uint32_t boff[2];
#pragma unroll
    for (int i = 0; i < 2; i++) {
        int u = tid + i * 256, row = u >> 2, cc = u & 3;
        pB[i] = g_wbf + (size_t)(cbase + row) * Dd + cc * 8;
        boff[i] = row * 64 + ((cc ^ ((row >> 1) & 3)) << 4);
    }
    // ---- ldmatrix lane offsets ----
    uint32_t offA[2], swA[2];
#pragma unroll
    for (int mt = 0; mt < 2; mt++) {
        int r = wm * 32 + mt * 16 + (lane & 15);
        offA[mt] = r * 64; swA[mt] = (r >> 1) & 3;
    }
    const uint32_t ccA = lane >> 4;
    uint32_t offB[4], swB[4];
#pragma unroll
    for (int nb = 0; nb < 4; nb++) {
        int r = wn * 64 + nb * 16 + ((lane >> 4) << 3) + (lane & 7);
        offB[nb] = r * 64; swB[nb] = (r >> 1) & 3;
    }
    const uint32_t ccB = (lane >> 3) & 1;

    float acc[2][8][4];
#pragma unroll
    for (int mt = 0; mt < 2; mt++)
#pragma unroll
        for (int nt = 0; nt < 8; nt++)
#pragma unroll
            for (int i = 0; i < 4; i++) acc[mt][nt][i] = 0.f;

    auto stsA = [&](const float4* v, uint32_t base) {
#pragma unroll
        for (int i = 0; i < 4; i++) {
            __nv_bfloat162 p0 = __floats2bfloat162_rn(v[i].x, v[i].y);
            __nv_bfloat162 p1 = __floats2bfloat162_rn(v[i].z, v[i].w);
            uint2 u;
            u.x = *(uint32_t*)&p0; u.y = *(uint32_t*)&p1;
            *(uint2*)(smem + (base - sb) + aoff[i]) = u;
        }
    };
    auto cpB = [&](int c, uint32_t base) {
#pragma unroll
        for (int i = 0; i < 2; i++) cp_async16(base + boff[i], pB[i] + c * KC);
        asm volatile("cp.async.commit_group;" ::: "memory");
    };

    // ---- prologue ----
    cpB(0, sb + 0 * SMB_STRIDE);
    cpB(1, sb + 1 * SMB_STRIDE);
    {
        float4 r0[4];
#pragma unroll
        for (int i = 0; i < 4; i++) r0[i] = *(const float4*)(pA[i]);
        stsA(r0, sb + SMA_OFF);
    }

    // ---- main loop ----
    for (int c = 0; c < NCH; c++) {
        const uint32_t bufB = sb + (uint32_t)(c % 3) * SMB_STRIDE;
        const uint32_t bufA = sb + SMA_OFF + (uint32_t)(c & 1) * SMA_STRIDE;

        if (c == NCH - 1) asm volatile("cp.async.wait_group 0;" ::: "memory");
        else              asm volatile("cp.async.wait_group 1;" ::: "memory");
        __syncthreads();

        float4 rA[4];
        const bool haveA = (c + 1 < NCH);
        if (haveA) {
#pragma unroll
            for (int i = 0; i < 4; i++) rA[i] = *(const float4*)(pA[i] + (c + 1) * KC);
        }
        if (c + 2 < NCH) cpB(c + 2, sb + (uint32_t)((c + 2) % 3) * SMB_STRIDE);

#pragma unroll
        for (int ks = 0; ks < 2; ks++) {
            uint32_t afrag[2][4], bfrag[4][4];
#pragma unroll
            for (int mt = 0; mt < 2; mt++)
                ldsm4(afrag[mt], bufA + offA[mt] + ((((uint32_t)ks * 2 + ccA) ^ swA[mt]) << 4));
#pragma unroll
            for (int nb = 0; nb < 4; nb++)
                ldsm4(bfrag[nb], bufB + offB[nb] + ((((uint32_t)ks * 2 + ccB) ^ swB[nb]) << 4));
#pragma unroll
            for (int mt = 0; mt < 2; mt++)
#pragma unroll
                for (int nt = 0; nt < 8; nt++)
                    mma_bf16(acc[mt][nt], afrag[mt], bfrag[nt >> 1][(nt & 1) * 2],
                             bfrag[nt >> 1][(nt & 1) * 2 + 1]);
        }
        if (haveA) stsA(rA, sb + SMA_OFF + (uint32_t)((c + 1) & 1) * SMA_STRIDE);
    }
    __syncthreads();   // everyone done reading stages; reuse smem for staging

    // ---- epilogue: bias + bf16 store (via smem transpose) + fused BN stats --
    __nv_bfloat16* stg = (__nv_bfloat16*)smem;   // [128][136]
#pragma unroll
    for (int nt = 0; nt < 8; nt++) {
        const int cn = wn * 64 + nt * 8 + 2 * lc;
        const float bv0 = sbias[cn], bv1 = sbias[cn + 1];
        float s0 = 0.f, q0 = 0.f, s1 = 0.f, q1 = 0.f;
#pragma unroll
        for (int mt = 0; mt < 2; mt++) {
            const int r0 = wm * 32 + mt * 16 + lr;
            const float f0 = (sridx[r0] >= 0) ? 1.f : 0.f;
            const float f1 = (sridx[r0 + 8] >= 0) ? 1.f : 0.f;
            const float h00 = acc[mt][nt][0] + bv0, h01 = acc[mt][nt][1] + bv1;
            const float h10 = acc[mt][nt][2] + bv0, h11 = acc[mt][nt][3] + bv1;
            __nv_bfloat162 p0 = __floats2bfloat162_rn(h00, h01);
            __nv_bfloat162 p1 = __floats2bfloat162_rn(h10, h11);
            *(uint32_t*)((char*)stg + r0 * 272 + cn * 2)       = *(uint32_t*)&p0;
            *(uint32_t*)((char*)stg + (r0 + 8) * 272 + cn * 2) = *(uint32_t*)&p1;
            s0 += f0 * h00 + f1 * h10;  q0 += f0 * h00 * h00 + f1 * h10 * h10;
            s1 += f0 * h01 + f1 * h11;  q1 += f0 * h01 * h01 + f1 * h11 * h11;
        }
#pragma unroll
        for (int off = 4; off < 32; off <<= 1) {
            s0 += __shfl_xor_sync(0xffffffffu, s0, off);
            q0 += __shfl_xor_sync(0xffffffffu, q0, off);
            s1 += __shfl_xor_sync(0xffffffffu, s1, off);
            q1 += __shfl_xor_sync(0xffffffffu, q1, off);
        }
        if (lr == 0) {
            atomicAdd(&g_sum[cbase + cn], s0);
            atomicAdd(&g_sumsq[cbase + cn], q0);
            atomicAdd(&g_sum[cbase + cn + 1], s1);
            atomicAdd(&g_sumsq[cbase + cn + 1], q1);
        }
    }
    __syncthreads();
    {
        const int row = tid >> 1, half = tid & 1;
        const char* src = (const char*)stg + row * 272 + half * 128;
        __nv_bfloat16* dst = g_hbf + (size_t)(rbase + row) * Hh + cbase + half * 64;
#pragma unroll
        for (int j = 0; j < 8; j++)
            *(uint4*)((char*)dst + j * 16) = *(const uint4*)(src + j * 16);
    }
}

// ---------------- K6: finalize BN affine -------------------------------------
__global__ void k_statsfin(const float* __restrict__ gamma, const float* __restrict__ beta) {
    __shared__ float nv;
    if (threadIdx.x == 0) {
        float s = 0.f;
        for (int b = 0; b < Bb; b++) s += g_cnt[b];
        nv = fmaxf(s, 1.f);
    }
    __syncthreads();
    int h = threadIdx.x;
    float mean = g_sum[h] / nv;
    float var  = fmaxf(g_sumsq[h] / nv - mean * mean, 0.f);
    float sc   = rsqrtf(var + EPSF) * gamma[h];
    g_scale[h] = sc;
    g_shift[h] = beta[h] - mean * sc;
}

// ---------------- K7: BN + ReLU + pool over compacted rows -------------------
__global__ __launch_bounds__(256) void k_pool() {
    __shared__ int sr[128];
    const int t = threadIdx.x;
    const int rbase = blockIdx.x * 128;
    if (t < 128) sr[t] = g_ridx[rbase + t];
    __syncthreads();
    if (sr[0] < 0) return;

    const float sc0 = g_scale[2 * t],     sh0 = g_shift[2 * t];
    const float sc1 = g_scale[2 * t + 1], sh1 = g_shift[2 * t + 1];
    float a0 = 0.f, a1 = 0.f;
    int curb = sr[0] >> 11;
    for (int i = 0; i < 128; i++) {
        int ri = sr[i];
        if (ri < 0) break;
        int bi = ri >> 11;
        if (bi != curb) {
            atomicAdd(&g_pool[curb * Hh + 2 * t], a0);
            atomicAdd(&g_pool[curb * Hh + 2 * t + 1], a1);
            a0 = a1 = 0.f; curb = bi;
        }
        uint32_t u = *(const uint32_t*)(g_hbf + (size_t)(rbase + i) * Hh + 2 * t);
        __nv_bfloat162 p = *(__nv_bfloat162*)&u;
        a0 += fmaxf(fmaf(__low2float(p),  sc0, sh0), 0.f);
        a1 += fmaxf(fmaf(__high2float(p), sc1, sh1), 0.f);
    }
    atomicAdd(&g_pool[curb * Hh + 2 * t], a0);
    atomicAdd(&g_pool[curb * Hh + 2 * t + 1], a1);
}

// ---------------- K8: tiny GEMM pooled @ W2 + b2 -----------------------------
__global__ __launch_bounds__(512) void k_out(const float* __restrict__ W2,
                                             const float* __restrict__ b2,
                                             float* __restrict__ out) {
    __shared__ float p[Hh];
    const int b = blockIdx.x, t = threadIdx.x;
    const float craw = g_cnt[b];
    p[t] = g_pool[b * Hh + t] / fmaxf(craw, 1.f);
    __syncthreads();
    float acc = (craw > 0.f) ? b2[t] : 0.f;
#pragma unroll 8
    for (int k = 0; k < Hh; k++) acc = fmaf(p[k], W2[(size_t)k * Hh + t], acc);
    out[b * Hh + t] = acc;
}

// ---------------- launch -----------------------------------------------------
extern "C" void kernel_launch(void* const* d_in, const int* in_sizes, int n_in,
                              void* d_out, int out_size) {
    const float* hidden = (const float*)d_in[0];
    const int*   mask   = (const int*)d_in[1];
    const float* W1     = (const float*)d_in[2];
    const float* b1     = (const float*)d_in[3];
    const float* gamma  = (const float*)d_in[4];
    const float* beta   = (const float*)d_in[5];
    const float* W2     = (const float*)d_in[6];
    const float* b2     = (const float*)d_in[7];
    float*       out    = (float*)d_out;

    k_zero<<<(BL + 128 + 255) / 256, 256>>>();
    k_counts<<<Bb, 256>>>(mask);
    k_offsets<<<1, 32>>>();
    k_compact<<<Bb, 256>>>(mask);
    k_cvtW<<<dim3(Dd / 32, Hh / 32), 256>>>(W1);
    k_gemm<<<dim3(Hh / 128, BL / 128), 256, SM_TOT>>>(hidden, b1);
    k_statsfin<<<1, Hh>>>(gamma, beta);
    k_pool<<<BL / 128, 256>>>();
    k_out<<<Bb, Hh>>>(W2, b2, out);
}

// round 7
// speedup vs baseline: 2.6295x; 1.0138x over previous
#include <cuda_runtime.h>
#include <cuda_bf16.h>
#include <cstdint>

#define Bb   32
#define Ll   2048
#define Dd   768
#define Hh   512
#define BL   (Bb * Ll)
#define EPSF 1e-5f
#define NCH  24              // 768 / 32
#define KC   32

// ---------------- scratch ----------------------------------------------------
__device__ __nv_bfloat16 g_wbf[(size_t)Hh * Dd];         // W1^T [N=512][K=768] bf16
__device__ __nv_bfloat16 g_hbf[(size_t)(BL + 128) * Hh]; // compacted h, bf16
__device__ int   g_ridx[BL + 128];
__device__ int   g_icnt[Bb];
__device__ int   g_cursor[Bb];
__device__ int   g_ntot;
__device__ float g_cnt[Bb];
__device__ float g_sum[Hh], g_sumsq[Hh], g_scale[Hh], g_shift[Hh];
__device__ float g_pool[Bb * Hh];

// ---------------- smem layout (GEMM) -----------------------------------------
#define SMB_STRIDE 8192      // B stage: 128 n-rows x 64 B
#define SMA_OFF    24576     // 3 B stages first
#define SMA_STRIDE 8192      // A stage: 128 m-rows x 64 B
#define SM_EXTRA   40960     // sridx(512B) + sbias(512B)
#define SM_TOT     41984

// ---------------- PTX helpers ------------------------------------------------
__device__ __forceinline__ uint32_t smem_u32(const void* p) {
    uint32_t a;
    asm("{ .reg .u64 t; cvta.to.shared.u64 t, %1; cvt.u32.u64 %0, t; }" : "=r"(a) : "l"(p));
    return a;
}
__device__ __forceinline__ void cp_async16(uint32_t dst, const void* src) {
    asm volatile("cp.async.cg.shared.global [%0], [%1], 16;" :: "r"(dst), "l"(src) : "memory");
}
__device__ __forceinline__ void ldsm4(uint32_t* r, uint32_t addr) {
    asm volatile("ldmatrix.sync.aligned.m8n8.x4.shared.b16 {%0,%1,%2,%3}, [%4];"
                 : "=r"(r[0]), "=r"(r[1]), "=r"(r[2]), "=r"(r[3]) : "r"(addr));
}
__device__ __forceinline__ void mma_bf16(float* c, const uint32_t* a, uint32_t b0, uint32_t b1) {
    asm volatile(
        "mma.sync.aligned.m16n8k16.row.col.f32.bf16.bf16.f32 "
        "{%0,%1,%2,%3}, {%4,%5,%6,%7}, {%8,%9}, {%0,%1,%2,%3};"
        : "+f"(c[0]), "+f"(c[1]), "+f"(c[2]), "+f"(c[3])
        : "r"(a[0]), "r"(a[1]), "r"(a[2]), "r"(a[3]), "r"(b0), "r"(b1));
}

// ---------------- K0: fused prep (W1 cvt/transpose | counts | zero) ----------
__global__ __launch_bounds__(256) void k_prep(const float* __restrict__ W1,
                                              const int* __restrict__ mask) {
    __shared__ float tile[32][33];
    __shared__ int   red[256];
    const int bid = blockIdx.x, t = threadIdx.x;

    if (bid < 384) {                       // ---- W1 -> bf16 transposed [N][K]
        const int kb = (bid % 24) * 32, nb = (bid / 24) * 32;
        const int tx = t & 31, ty = t >> 5;  // 32 x 8
#pragma unroll
        for (int j = 0; j < 4; j++)
            tile[ty + 8 * j][tx] = W1[(size_t)(kb + ty + 8 * j) * Hh + nb + tx];
        __syncthreads();
#pragma unroll
        for (int j = 0; j < 4; j++)
            g_wbf[(size_t)(nb + ty + 8 * j) * Dd + kb + tx] =
                __float2bfloat16(tile[tx][ty + 8 * j]);
    } else if (bid < 416) {                // ---- per-batch valid counts
        const int b = bid - 384;
        int s = 0;
        for (int l = t; l < Ll; l += 256) s += mask[b * Ll + l];
        red[t] = s;
        __syncthreads();
        for (int off = 128; off; off >>= 1) {
            if (t < off) red[t] += red[t + off];
            __syncthreads();
        }
        if (t == 0) { g_icnt[b] = red[0]; g_cnt[b] = (float)red[0]; }
    } else {                               // ---- zero accumulators
        const int i = (bid - 416) * 256 + t;       // 64 blocks -> 16384
        g_pool[i] = 0.f;
        if (i < Hh) { g_sum[i] = 0.f; g_sumsq[i] = 0.f; }
    }
}

// ---------------- K1: exclusive offsets (1 warp) ------------------------------
__global__ void k_offsets() {
    int l = threadIdx.x;
    int c = g_icnt[l], x = c;
    for (int o = 1; o < 32; o <<= 1) {
        int y = __shfl_up_sync(0xffffffffu, x, o);
        if (l >= o) x += y;
    }
    g_cursor[l] = x - c;
    if (l == 31) g_ntot = x;
}

// ---------------- K2: parallel compaction (order-free within batch) ----------
__global__ __launch_bounds__(256) void k_compact(const int* __restrict__ mask) {
    const int b = blockIdx.x >> 3;
    const int gi = b * Ll + (blockIdx.x & 7) * 256 + threadIdx.x;
    const int lane = threadIdx.x & 31;
    const int v = mask[gi];
    const unsigned bal = __ballot_sync(0xffffffffu, v);
    int base = 0;
    if (lane == 0 && bal) base = atomicAdd(&g_cursor[b], __popc(bal));
    base = __shfl_sync(0xffffffffu, base, 0);
    if (v) g_ridx[base + __popc(bal & ((1u << lane) - 1u))] = gi;
}

// ---------------- K3: bf16 mma.sync GEMM + bias + fused stats ----------------
__global__ __launch_bounds__(256, 2) void k_gemm(const float* __restrict__ A,
                                                 const float* __restrict__ b1) {
    const int rbase = blockIdx.y * 128;
    const int ntot  = __ldg(&g_ntot);
    if (rbase >= ntot) return;

    extern __shared__ char smem[];
    const uint32_t sb = smem_u32(smem);
    const int tid = threadIdx.x;
    const int w = tid >> 5, lane = tid & 31;
    const int lr = lane >> 2, lc = lane & 3;
    const int wm = w & 3, wn = w >> 2;
    const int cbase = blockIdx.x * 128;

    int*   sridx = (int*)(smem + SM_EXTRA);
    float* sbias = (float*)(smem + SM_EXTRA + 512);
    if (tid < 128) {
        const int gr = rbase + tid;
        sridx[tid] = (gr < ntot) ? g_ridx[gr] : -1;
        sbias[tid] = b1[cbase + tid];
    }
    __syncthreads();

    // ---- per-thread loader precompute ----
    const float* pA[4]; uint32_t aoff[4];
#pragma unroll
    for (int i = 0; i < 4; i++) {
        int u = tid + i * 256, row = u >> 3, q = u & 7;
        int ridx = sridx[row]; if (ridx < 0) ridx = 0;
        pA[i] = A + (size_t)ridx * Dd + q * 4;
        int c = q >> 1, sub = q & 1;
        aoff[i] = row * 64 + ((c ^ ((row >> 1) & 3)) << 4) + sub * 8;
    }
    const __nv_bfloat16* pB[2]; uint32_t boff[2];
#pragma unroll
    for (int i = 0; i < 2; i++) {
        int u = tid + i * 256, row = u >> 2, cc = u & 3;
        pB[i] = g_wbf + (size_t)(cbase + row) * Dd + cc * 8;
        boff[i] = row * 64 + ((cc ^ ((row >> 1) & 3)) << 4);
    }
    // ---- ldmatrix lane offsets ----
    uint32_t offA[2], swA[2];
#pragma unroll
    for (int mt = 0; mt < 2; mt++) {
        int r = wm * 32 + mt * 16 + (lane & 15);
        offA[mt] = r * 64; swA[mt] = (r >> 1) & 3;
    }
    const uint32_t ccA = lane >> 4;
    uint32_t offB[4], swB[4];
#pragma unroll
    for (int nb = 0; nb < 4; nb++) {
        int r = wn * 64 + nb * 16 + ((lane >> 4) << 3) + (lane & 7);
        offB[nb] = r * 64; swB[nb] = (r >> 1) & 3;
    }
    const uint32_t ccB = (lane >> 3) & 1;

    float acc[2][8][4];
#pragma unroll
    for (int mt = 0; mt < 2; mt++)
#pragma unroll
        for (int nt = 0; nt < 8; nt++)
#pragma unroll
            for (int i = 0; i < 4; i++) acc[mt][nt][i] = 0.f;

    auto stsA = [&](const float4* v, uint32_t base) {
#pragma unroll
        for (int i = 0; i < 4; i++) {
            __nv_bfloat162 p0 = __floats2bfloat162_rn(v[i].x, v[i].y);
            __nv_bfloat162 p1 = __floats2bfloat162_rn(v[i].z, v[i].w);
            uint2 u;
            u.x = *(uint32_t*)&p0; u.y = *(uint32_t*)&p1;
            *(uint2*)(smem + (base - sb) + aoff[i]) = u;
        }
    };
    auto cpB = [&](int c, uint32_t base) {
#pragma unroll
        for (int i = 0; i < 2; i++) cp_async16(base + boff[i], pB[i] + c * KC);
        asm volatile("cp.async.commit_group;" ::: "memory");
    };

    // ---- prologue ----
    cpB(0, sb + 0 * SMB_STRIDE);
    cpB(1, sb + 1 * SMB_STRIDE);
    {
        float4 r0[4];
#pragma unroll
        for (int i = 0; i < 4; i++) r0[i] = *(const float4*)(pA[i]);
        stsA(r0, sb + SMA_OFF);
    }

    // ---- main loop ----
    for (int c = 0; c < NCH; c++) {
        const uint32_t bufB = sb + (uint32_t)(c % 3) * SMB_STRIDE;
        const uint32_t bufA = sb + SMA_OFF + (uint32_t)(c & 1) * SMA_STRIDE;

        if (c == NCH - 1) asm volatile("cp.async.wait_group 0;" ::: "memory");
        else              asm volatile("cp.async.wait_group 1;" ::: "memory");
        __syncthreads();

        float4 rA[4];
        const bool haveA = (c + 1 < NCH);
        if (haveA) {
#pragma unroll
            for (int i = 0; i < 4; i++) rA[i] = *(const float4*)(pA[i] + (c + 1) * KC);
        }
        if (c + 2 < NCH) cpB(c + 2, sb + (uint32_t)((c + 2) % 3) * SMB_STRIDE);

#pragma unroll
        for (int ks = 0; ks < 2; ks++) {
            uint32_t afrag[2][4], bfrag[4][4];
#pragma unroll
            for (int mt = 0; mt < 2; mt++)
                ldsm4(afrag[mt], bufA + offA[mt] + ((((uint32_t)ks * 2 + ccA) ^ swA[mt]) << 4));
#pragma unroll
            for (int nb = 0; nb < 4; nb++)
                ldsm4(bfrag[nb], bufB + offB[nb] + ((((uint32_t)ks * 2 + ccB) ^ swB[nb]) << 4));
#pragma unroll
            for (int mt = 0; mt < 2; mt++)
#pragma unroll
                for (int nt = 0; nt < 8; nt++)
                    mma_bf16(acc[mt][nt], afrag[mt], bfrag[nt >> 1][(nt & 1) * 2],
                             bfrag[nt >> 1][(nt & 1) * 2 + 1]);
        }
        if (haveA) stsA(rA, sb + SMA_OFF + (uint32_t)((c + 1) & 1) * SMA_STRIDE);
    }
    __syncthreads();   // everyone done reading stages; reuse smem for staging

    // ---- epilogue: bias + bf16 store (via smem transpose) + fused BN stats --
    __nv_bfloat16* stg = (__nv_bfloat16*)smem;   // [128][136]
#pragma unroll
    for (int nt = 0; nt < 8; nt++) {
        const int cn = wn * 64 + nt * 8 + 2 * lc;
        const float bv0 = sbias[cn], bv1 = sbias[cn + 1];
        float s0 = 0.f, q0 = 0.f, s1 = 0.f, q1 = 0.f;
#pragma unroll
        for (int mt = 0; mt < 2; mt++) {
            const int r0 = wm * 32 + mt * 16 + lr;
            const float f0 = (sridx[r0] >= 0) ? 1.f : 0.f;
            const float f1 = (sridx[r0 + 8] >= 0) ? 1.f : 0.f;
            const float h00 = acc[mt][nt][0] + bv0, h01 = acc[mt][nt][1] + bv1;
            const float h10 = acc[mt][nt][2] + bv0, h11 = acc[mt][nt][3] + bv1;
            __nv_bfloat162 p0 = __floats2bfloat162_rn(h00, h01);
            __nv_bfloat162 p1 = __floats2bfloat162_rn(h10, h11);
            *(uint32_t*)((char*)stg + r0 * 272 + cn * 2)       = *(uint32_t*)&p0;
            *(uint32_t*)((char*)stg + (r0 + 8) * 272 + cn * 2) = *(uint32_t*)&p1;
            s0 += f0 * h00 + f1 * h10;  q0 += f0 * h00 * h00 + f1 * h10 * h10;
            s1 += f0 * h01 + f1 * h11;  q1 += f0 * h01 * h01 + f1 * h11 * h11;
        }
#pragma unroll
        for (int off = 4; off < 32; off <<= 1) {
            s0 += __shfl_xor_sync(0xffffffffu, s0, off);
            q0 += __shfl_xor_sync(0xffffffffu, q0, off);
            s1 += __shfl_xor_sync(0xffffffffu, s1, off);
            q1 += __shfl_xor_sync(0xffffffffu, q1, off);
        }
        if (lr == 0) {
            atomicAdd(&g_sum[cbase + cn], s0);
            atomicAdd(&g_sumsq[cbase + cn], q0);
            atomicAdd(&g_sum[cbase + cn + 1], s1);
            atomicAdd(&g_sumsq[cbase + cn + 1], q1);
        }
    }
    __syncthreads();
    {
        const int row = tid >> 1, half = tid & 1;
        const char* src = (const char*)stg + row * 272 + half * 128;
        __nv_bfloat16* dst = g_hbf + (size_t)(rbase + row) * Hh + cbase + half * 64;
#pragma unroll
        for (int j = 0; j < 8; j++)
            *(uint4*)((char*)dst + j * 16) = *(const uint4*)(src + j * 16);
    }
}

// ---------------- K4: finalize BN affine -------------------------------------
__global__ void k_statsfin(const float* __restrict__ gamma, const float* __restrict__ beta) {
    __shared__ float nv;
    if (threadIdx.x == 0) {
        float s = 0.f;
        for (int b = 0; b < Bb; b++) s += g_cnt[b];
        nv = fmaxf(s, 1.f);
    }
    __syncthreads();
    int h = threadIdx.x;
    float mean = g_sum[h] / nv;
    float var  = fmaxf(g_sumsq[h] / nv - mean * mean, 0.f);
    float sc   = rsqrtf(var + EPSF) * gamma[h];
    g_scale[h] = sc;
    g_shift[h] = beta[h] - mean * sc;
}

// ---------------- K5: BN + ReLU + pool over compacted rows -------------------
__global__ __launch_bounds__(256) void k_pool() {
    const int rbase = blockIdx.x * 128;
    const int ntot = __ldg(&g_ntot);
    if (rbase >= ntot) return;

    __shared__ int sr[128];
    const int t = threadIdx.x;
    if (t < 128) {
        const int gr = rbase + t;
        sr[t] = (gr < ntot) ? g_ridx[gr] : -1;
    }
    __syncthreads();

    const float sc0 = g_scale[2 * t],     sh0 = g_shift[2 * t];
    const float sc1 = g_scale[2 * t + 1], sh1 = g_shift[2 * t + 1];
    float a0 = 0.f, a1 = 0.f;
    int curb = sr[0] >> 11;
    for (int i = 0; i < 128; i++) {
        int ri = sr[i];
        if (ri < 0) break;
        int bi = ri >> 11;
        if (bi != curb) {
            atomicAdd(&g_pool[curb * Hh + 2 * t], a0);
            atomicAdd(&g_pool[curb * Hh + 2 * t + 1], a1);
            a0 = a1 = 0.f; curb = bi;
        }
        uint32_t u = *(const uint32_t*)(g_hbf + (size_t)(rbase + i) * Hh + 2 * t);
        __nv_bfloat162 p = *(__nv_bfloat162*)&u;
        a0 += fmaxf(fmaf(__low2float(p),  sc0, sh0), 0.f);
        a1 += fmaxf(fmaf(__high2float(p), sc1, sh1), 0.f);
    }
    atomicAdd(&g_pool[curb * Hh + 2 * t], a0);
    atomicAdd(&g_pool[curb * Hh + 2 * t + 1], a1);
}

// ---------------- K6: tiny GEMM pooled @ W2 + b2 -----------------------------
__global__ __launch_bounds__(512) void k_out(const float* __restrict__ W2,
                                             const float* __restrict__ b2,
                                             float* __restrict__ out) {
    __shared__ float p[Hh];
    const int b = blockIdx.x, t = threadIdx.x;
    const float craw = g_cnt[b];
    p[t] = g_pool[b * Hh + t] / fmaxf(craw, 1.f);
    __syncthreads();
    float acc = (craw > 0.f) ? b2[t] : 0.f;
#pragma unroll 8
    for (int k = 0; k < Hh; k++) acc = fmaf(p[k], W2[(size_t)k * Hh + t], acc);
    out[b * Hh + t] = acc;
}

// ---------------- launch -----------------------------------------------------
extern "C" void kernel_launch(void* const* d_in, const int* in_sizes, int n_in,
                              void* d_out, int out_size) {
    const float* hidden = (const float*)d_in[0];
    const int*   mask   = (const int*)d_in[1];
    const float* W1     = (const float*)d_in[2];
    const float* b1     = (const float*)d_in[3];
    const float* gamma  = (const float*)d_in[4];
    const float* beta   = (const float*)d_in[5];
    const float* W2     = (const float*)d_in[6];
    const float* b2     = (const float*)d_in[7];
    float*       out    = (float*)d_out;

    k_prep<<<480, 256>>>(W1, mask);
    k_offsets<<<1, 32>>>();
    k_compact<<<BL / 256, 256>>>(mask);
    k_gemm<<<dim3(Hh / 128, BL / 128), 256, SM_TOT>>>(hidden, b1);
    k_statsfin<<<1, Hh>>>(gamma, beta);
    k_pool<<<BL / 128, 256>>>();
    k_out<<<Bb, Hh>>>(W2, b2, out);
}